// round 15
// baseline (speedup 1.0000x reference)
#include <cuda_runtime.h>
#include <cstdint>

// ---------------------------------------------------------------------------
// Problem constants
// ---------------------------------------------------------------------------
#define BB    32
#define TT    1024
#define CC    512
#define DD    256
#define UU    256
#define OO    256
#define MTOT  (BB*TT)          // 32768

__device__ float g_xin[(size_t)MTOT * DD];
__device__ float g_xz [(size_t)MTOT * 4 * UU];
__device__ float g_hs [(size_t)MTOT * UU];

// 1 noop: keeps LSTM at the ncu capture slot
__global__ void noop_kernel(int* p) { if (p) *p = 0; }

#define FMA2(acc, a, b) \
    asm("fma.rn.f32x2 %0, %1, %2, %0;" : "+l"(acc) : "l"(a), "l"(b))

// ---------------------------------------------------------------------------
// GEMM v5: BM=128, BN=128, BK=16, 256 threads, 8x8 per thread, FMA2 over
// M-pairs, double-buffered SMEM. LDS bytes/MAC: 1.0 (was 1.5) -> LDS floor
// and FMA2 floor balanced (~128 cyc/kk each). k-order per output unchanged
// -> rel_err bit-identical.
// ---------------------------------------------------------------------------
__global__ __launch_bounds__(256) void gemm_bias_kernel(
    const float* __restrict__ A, const float* __restrict__ W,
    const float* __restrict__ bias, float* __restrict__ C,
    int M, int N, int K)
{
    __shared__ float As[2][16][128];   // [buf][k][m] (transposed A)
    __shared__ float Bs[2][16][128];   // [buf][k][n]

    const int tid = threadIdx.x;
    const int tx  = tid & 15;          // n-dir: 8 cols at tx*8
    const int ty  = tid >> 4;          // m-dir: 8 rows at ty*8
    const int m0  = blockIdx.y * 128;
    const int n0  = blockIdx.x * 128;

    const int arow = tid >> 1;           // 0..127
    const int acol = (tid & 1) * 8;      // 0 or 8
    const int brow = tid >> 4;           // 0..15
    const int bcol = (tid & 15) * 8;     // 0..120

    // acc2[mp][j]: packed {C[ty*8+2mp][j], C[ty*8+2mp+1][j]}, j = n offset 0..7
    unsigned long long acc2[4][8];
    #pragma unroll
    for (int i = 0; i < 4; i++)
        #pragma unroll
        for (int j = 0; j < 8; j++) acc2[i][j] = 0ull;

    // ---- prologue: tile 0 ----
    float4 ra0 = *(const float4*)&A[(size_t)(m0 + arow) * K + acol];
    float4 ra1 = *(const float4*)&A[(size_t)(m0 + arow) * K + acol + 4];
    float4 rb0 = *(const float4*)&W[(size_t)brow * N + n0 + bcol];
    float4 rb1 = *(const float4*)&W[(size_t)brow * N + n0 + bcol + 4];
    {
        As[0][acol + 0][arow] = ra0.x;
        As[0][acol + 1][arow] = ra0.y;
        As[0][acol + 2][arow] = ra0.z;
        As[0][acol + 3][arow] = ra0.w;
        As[0][acol + 4][arow] = ra1.x;
        As[0][acol + 5][arow] = ra1.y;
        As[0][acol + 6][arow] = ra1.z;
        As[0][acol + 7][arow] = ra1.w;
        *(float4*)&Bs[0][brow][bcol]     = rb0;
        *(float4*)&Bs[0][brow][bcol + 4] = rb1;
    }
    __syncthreads();

    const int ntiles = K >> 4;
    for (int it = 0; it < ntiles; it++) {
        const int cur = it & 1;
        const int nxt = cur ^ 1;
        const bool more = (it + 1 < ntiles);

        // LDG next tile FIRST (latency overlaps compute)
        if (more) {
            const int kt = (it + 1) << 4;
            ra0 = *(const float4*)&A[(size_t)(m0 + arow) * K + kt + acol];
            ra1 = *(const float4*)&A[(size_t)(m0 + arow) * K + kt + acol + 4];
            rb0 = *(const float4*)&W[(size_t)(kt + brow) * N + n0 + bcol];
            rb1 = *(const float4*)&W[(size_t)(kt + brow) * N + n0 + bcol + 4];
        }

        #pragma unroll
        for (int kk = 0; kk < 16; kk++) {
            // A: 4 packed m-pairs (transposed layout = pairs for free)
            ulonglong2 ap0 = *(const ulonglong2*)&As[cur][kk][ty * 8];
            ulonglong2 ap1 = *(const ulonglong2*)&As[cur][kk][ty * 8 + 4];
            // B: 8 scalars
            float4 b0 = *(const float4*)&Bs[cur][kk][tx * 8];
            float4 b1 = *(const float4*)&Bs[cur][kk][tx * 8 + 4];
            unsigned long long bb[8];
            {
                const float bs[8] = {b0.x, b0.y, b0.z, b0.w,
                                     b1.x, b1.y, b1.z, b1.w};
                #pragma unroll
                for (int j = 0; j < 8; j++) {
                    unsigned u = __float_as_uint(bs[j]);
                    asm("mov.b64 %0, {%1, %1};" : "=l"(bb[j]) : "r"(u));
                }
            }
            const unsigned long long ap[4] = {ap0.x, ap0.y, ap1.x, ap1.y};
            #pragma unroll
            for (int mp = 0; mp < 4; mp++)
                #pragma unroll
                for (int j = 0; j < 8; j++)
                    FMA2(acc2[mp][j], ap[mp], bb[j]);
        }

        if (more) {
            As[nxt][acol + 0][arow] = ra0.x;
            As[nxt][acol + 1][arow] = ra0.y;
            As[nxt][acol + 2][arow] = ra0.z;
            As[nxt][acol + 3][arow] = ra0.w;
            As[nxt][acol + 4][arow] = ra1.x;
            As[nxt][acol + 5][arow] = ra1.y;
            As[nxt][acol + 6][arow] = ra1.z;
            As[nxt][acol + 7][arow] = ra1.w;
            *(float4*)&Bs[nxt][brow][bcol]     = rb0;
            *(float4*)&Bs[nxt][brow][bcol + 4] = rb1;
        }
        __syncthreads();
    }

    // epilogue: unpack pairs, add bias, store two m-rows per mp
    float4 bv0 = *(const float4*)&bias[n0 + tx * 8];
    float4 bv1 = *(const float4*)&bias[n0 + tx * 8 + 4];
    const float bbv[8] = {bv0.x, bv0.y, bv0.z, bv0.w,
                          bv1.x, bv1.y, bv1.z, bv1.w};
    #pragma unroll
    for (int mp = 0; mp < 4; mp++) {
        float lo[8], hi[8];
        #pragma unroll
        for (int j = 0; j < 8; j++) {
            unsigned l_, h_;
            asm("mov.b64 {%0, %1}, %2;" : "=r"(l_), "=r"(h_) : "l"(acc2[mp][j]));
            lo[j] = __uint_as_float(l_) + bbv[j];
            hi[j] = __uint_as_float(h_) + bbv[j];
        }
        float* cp0 = &C[(size_t)(m0 + ty * 8 + 2 * mp) * N + n0 + tx * 8];
        float* cp1 = &C[(size_t)(m0 + ty * 8 + 2 * mp + 1) * N + n0 + tx * 8];
        *(float4*)cp0       = make_float4(lo[0], lo[1], lo[2], lo[3]);
        *(float4*)(cp0 + 4) = make_float4(lo[4], lo[5], lo[6], lo[7]);
        *(float4*)cp1       = make_float4(hi[0], hi[1], hi[2], hi[3]);
        *(float4*)(cp1 + 4) = make_float4(hi[4], hi[5], hi[6], hi[7]);
    }
}

// ---------------------------------------------------------------------------
// LSTM scan: EXACT R14/R13/R9 version (proven best). Unchanged.
// ---------------------------------------------------------------------------
#define CLS 8
#define LSTM_THREADS 256

__device__ __forceinline__ float sigm_f(float x) {
    return 1.f / (1.f + __expf(-x));
}
__device__ __forceinline__ float tanh_f(float x) {
    return 2.f / (1.f + __expf(-2.f * x)) - 1.f;
}

#define MBAR_INIT(addr, cnt) \
    asm volatile("mbarrier.init.shared.b64 [%0], %1;" :: "r"(addr), "r"(cnt) : "memory")

#define MBAR_EXPECT_TX(addr, tx) \
    asm volatile("mbarrier.arrive.expect_tx.shared.b64 _, [%0], %1;" :: "r"(addr), "r"(tx) : "memory")

#define MBAR_WAIT(addr, par) do {                                                  \
    asm volatile("{\n\t.reg .pred P;\n"                                            \
                 "W_%=:\n\t"                                                       \
                 "mbarrier.try_wait.parity.acquire.cluster.shared::cta.b64 "       \
                 "P, [%0], %1, 0x80;\n\t"                                          \
                 "@!P bra W_%=;\n\t}"                                              \
                 :: "r"(addr), "r"(par) : "memory");                               \
} while (0)

__global__ void __cluster_dims__(CLS, 1, 1) __launch_bounds__(LSTM_THREADS, 1)
lstm_kernel(const float* __restrict__ xz, const float* __restrict__ R,
            float* __restrict__ hs)
{
    __shared__ __align__(16) float h2[2 * 512];         // [buf][k=256][b=2]
    __shared__ __align__(16) float parts[2][16 * 128];  // [buf][w*2+b][c=128]
    __shared__ __align__(16) float hstage[64];          // [u=32][b=2]
    __shared__ __align__(8)  unsigned long long mbar[16]; // [buf][src=8]

    const int tid  = threadIdx.x;
    const int rank = blockIdx.x;
    const int b0   = blockIdx.y * 2;
    const int w    = tid >> 5;
    const int l    = tid & 31;

    // ---- R slice -> registers: thread (w,l) holds k=32w..32w+32, cols 4l..4l+3
    const int gate = l >> 3;
    const int cb   = (4 * l) & 31;
    const int gcol = gate * 256 + rank * 32 + cb;
    ulonglong2 Rreg[32];
    #pragma unroll
    for (int j = 0; j < 32; j++)
        Rreg[j] = *(const ulonglong2*)&R[(size_t)(w * 32 + j) * 1024 + gcol];

    for (int i = tid; i < 1024; i += LSTM_THREADS) h2[i] = 0.f;

    const unsigned mb0 = (unsigned)__cvta_generic_to_shared(&mbar[0]);
    if (tid == 0) {
        #pragma unroll
        for (int i = 0; i < 16; i++) {
            MBAR_INIT(mb0 + i * 8, 1);
            MBAR_EXPECT_TX(mb0 + i * 8, 256);
        }
        asm volatile("fence.mbarrier_init.release.cluster;" ::: "memory");
    }
    __syncthreads();
    asm volatile("barrier.cluster.arrive.aligned;" ::: "memory");
    asm volatile("barrier.cluster.wait.aligned;"   ::: "memory");

    const int gb = tid >> 5;            // gate-thread batch  (tid<64)
    const int gu = tid & 31;            // gate-thread unit
    float creg = 0.f;
    int ph0 = 0, ph1 = 0;

    const unsigned dst_l[2] = {
        (unsigned)__cvta_generic_to_shared(&h2[0 * 512 + rank * 64]),
        (unsigned)__cvta_generic_to_shared(&h2[1 * 512 + rank * 64])};
    const unsigned src_l =
        (unsigned)__cvta_generic_to_shared(&hstage[0]);

    // hoisted remote addresses for the bulk push (threads 0..7)
    unsigned rdl = 0, rml = 0;
    if (tid < 8) {
        asm volatile("mapa.shared::cluster.u32 %0, %1, %2;"
                     : "=r"(rdl) : "r"(dst_l[0]), "r"(tid));
        asm volatile("mapa.shared::cluster.u32 %0, %1, %2;"
                     : "=r"(rml) : "r"(mb0 + (unsigned)(rank * 8)), "r"(tid));
    }

    // ---- xz prefetch pipeline: load t=0 now; inside step t we load t+1 ----
    const float* xzp = (tid < 64)
        ? &xz[((size_t)(b0 + gb) * TT) * 1024 + rank * 32 + gu] : xz;
    float xzv0 = 0.f, xzv1 = 0.f, xzv2 = 0.f, xzv3 = 0.f;
    if (tid < 64) {
        xzv0 = xzp[0];
        xzv1 = xzp[256];
        xzv2 = xzp[512];
        xzv3 = xzp[768];
    }

    for (int t = 0; t < TT; t++) {
        const int pb = t & 1;

        // prefetch xz for t+1 (consumed in NEXT step's gate phase)
        float nx0 = 0.f, nx1 = 0.f, nx2 = 0.f, nx3 = 0.f;
        if (tid < 64 && t + 1 < TT) {
            const float* p = xzp + (size_t)(t + 1) * 1024;
            nx0 = p[0];
            nx1 = p[256];
            nx2 = p[512];
            nx3 = p[768];
        }

        // wait ONLY for our source slice (rank w -> units 32w..32w+32)
        if (t > 0) {
            const unsigned m = mb0 + (unsigned)((pb * 8 + w) * 8);
            if (pb) { MBAR_WAIT(m, ph1); ph1 ^= 1; }
            else    { MBAR_WAIT(m, ph0); ph0 ^= 1; }
            if (l == 0) MBAR_EXPECT_TX(m, 256);   // re-arm for t+2
        }

        // ---- MMA: z_partial over k in [32w,32w+32), cols 4l..4l+3, b=0,1
        unsigned long long a00 = 0ull, a01 = 0ull, a10 = 0ull, a11 = 0ull;
        const float2* hb = (const float2*)(h2 + pb * 512) + w * 32;
        #pragma unroll
        for (int j = 0; j < 32; j++) {
            float2 hh = hb[j];
            unsigned hx = __float_as_uint(hh.x);
            unsigned hy = __float_as_uint(hh.y);
            unsigned long long hp0, hp1;
            asm("mov.b64 %0, {%1, %1};" : "=l"(hp0) : "r"(hx));
            asm("mov.b64 %0, {%1, %1};" : "=l"(hp1) : "r"(hy));
            FMA2(a00, Rreg[j].x, hp0);
            FMA2(a01, Rreg[j].x, hp1);
            FMA2(a10, Rreg[j].y, hp0);
            FMA2(a11, Rreg[j].y, hp1);
        }
        {
            float* pbuf = parts[pb];
            unsigned p0, p1, p2, p3;
            asm("mov.b64 {%0, %1}, %2;" : "=r"(p0), "=r"(p1) : "l"(a00));
            asm("mov.b64 {%0, %1}, %2;" : "=r"(p2), "=r"(p3) : "l"(a10));
            *(float4*)&pbuf[(w * 2 + 0) * 128 + 4 * l] =
                make_float4(__uint_as_float(p0), __uint_as_float(p1),
                            __uint_as_float(p2), __uint_as_float(p3));
            asm("mov.b64 {%0, %1}, %2;" : "=r"(p0), "=r"(p1) : "l"(a01));
            asm("mov.b64 {%0, %1}, %2;" : "=r"(p2), "=r"(p3) : "l"(a11));
            *(float4*)&pbuf[(w * 2 + 1) * 128 + 4 * l] =
                make_float4(__uint_as_float(p0), __uint_as_float(p1),
                            __uint_as_float(p2), __uint_as_float(p3));
        }

        if (w >= 2) {
            asm volatile("bar.arrive 2, 256;" ::: "memory");
            xzv0 = nx0; xzv1 = nx1; xzv2 = nx2; xzv3 = nx3;
            continue;                      // run ahead into next step
        }
        asm volatile("bar.sync 2, 256;" ::: "memory");

        // ---- gate phase (warps 0,1 == 64 gate threads) ----
        {
            const float* pbuf = parts[pb];
            float z0 = xzv0, z1 = xzv1, z2 = xzv2, z3 = xzv3;
            #pragma unroll
            for (int ww = 0; ww < 8; ww++) {
                const float* p = &pbuf[(ww * 2 + gb) * 128];
                z0 += p[gu];
                z1 += p[32 + gu];
                z2 += p[64 + gu];
                z3 += p[96 + gu];
            }
            float ig = sigm_f(z0);
            float fg = sigm_f(z1);
            float gg = tanh_f(z2);
            float og = sigm_f(z3);
            creg = fg * creg + ig * gg;
            float h = og * tanh_f(creg);

            if (t < TT - 1) {
                hstage[gu * 2 + gb] = h;
                asm volatile("bar.sync 1, 64;" ::: "memory");
                if (tid < 8) {
                    asm volatile("fence.proxy.async.shared::cta;" ::: "memory");
                    const int nb = pb ^ 1;
                    const unsigned rd = rdl + (unsigned)(nb * 2048);
                    const unsigned rm = rml + (unsigned)(nb * 64);
                    asm volatile(
                        "cp.async.bulk.shared::cluster.shared::cta"
                        ".mbarrier::complete_tx::bytes [%0], [%1], 256, [%2];"
                        :: "r"(rd), "r"(src_l), "r"(rm) : "memory");
                }
            }
            // global store off the critical path
            hs[((size_t)(b0 + gb) * TT + t) * UU + rank * 32 + gu] = h;
        }
        xzv0 = nx0; xzv1 = nx1; xzv2 = nx2; xzv3 = nx3;
    }

    asm volatile("barrier.cluster.arrive.aligned;" ::: "memory");
    asm volatile("barrier.cluster.wait.aligned;"   ::: "memory");
}

// ---------------------------------------------------------------------------
// launch
// ---------------------------------------------------------------------------
extern "C" void kernel_launch(void* const* d_in, const int* in_sizes, int n_in,
                              void* d_out, int out_size)
{
    const float* x      = (const float*)d_in[0];
    const float* w_in   = (const float*)d_in[1];
    const float* b_in   = (const float*)d_in[2];
    const float* kernel = (const float*)d_in[3];
    const float* rec_k  = (const float*)d_in[4];
    const float* bias   = (const float*)d_in[5];
    const float* w_out  = (const float*)d_in[6];
    const float* b_out  = (const float*)d_in[7];
    float* out = (float*)d_out;

    float *p_xin, *p_xz, *p_hs;
    cudaGetSymbolAddress((void**)&p_xin, g_xin);
    cudaGetSymbolAddress((void**)&p_xz,  g_xz);
    cudaGetSymbolAddress((void**)&p_hs,  g_hs);

    // 1 noop: LSTM stays at the ncu capture index
    noop_kernel<<<1, 32>>>(nullptr);

    // 1) xin = x @ w_in + b_in          [32768,512]x[512,256]
    gemm_bias_kernel<<<dim3(DD / 128, MTOT / 128), 256>>>(
        x, w_in, b_in, p_xin, MTOT, DD, CC);

    // 2) xz = xin @ kernel + bias       [32768,256]x[256,1024]
    gemm_bias_kernel<<<dim3((4 * UU) / 128, MTOT / 128), 256>>>(
        p_xin, kernel, bias, p_xz, MTOT, 4 * UU, DD);

    // 3) LSTM scan over T=1024
    lstm_kernel<<<dim3(CLS, BB / 2), LSTM_THREADS>>>(p_xz, rec_k, p_hs);

    // 4) out = hs @ w_out + b_out       [32768,256]x[256,256]
    gemm_bias_kernel<<<dim3(OO / 128, MTOT / 128), 256>>>(
        p_hs, w_out, b_out, out, MTOT, OO, UU);
}